// round 1
// baseline (speedup 1.0000x reference)
#include <cuda_runtime.h>
#include <math.h>

// Problem constants
#define BB 32
#define C3 1024
#define C4 2048
#define CTOT 3072
#define HH 28
#define HW 784
#define H4 14
#define HW4 196
#define LL 9
#define NA 312
#define NC 200

// Output layout (flattened concat of reference return tuple)
#define OFF_ATTR  0
#define OFF_CLASS (BB*NA)                  // 9984
#define OFF_MAPS  (OFF_CLASS + BB*NC)      // 16384
#define OFF_AF    (OFF_MAPS + BB*LL*HW)    // 242176

// Scratch (__device__ globals; no runtime allocation allowed)
__device__ __align__(16) float g_pab4[8 * BB * LL * HW4];   // l4 partial ab, 14x14 grid
__device__ __align__(16) float g_pab3[4 * BB * LL * HW];    // l3 partial ab, 28x28 grid
__device__ __align__(16) float g_ab4[BB * LL * HW4];        // reduced l4 ab
__device__ __align__(16) float g_mdown[BB * LL * HW4];      // adjoint-downsampled maps
__device__ __align__(16) float g_meanf[BB * CTOT];          // mean features
__device__ float g_asq[LL];

// ---------------------------------------------------------------------------
// a_sq[l] = sum_c conv_w[l][c]
__global__ void k_prep(const float* __restrict__ conv_w) {
    int warp = threadIdx.x >> 5, lane = threadIdx.x & 31;
    if (warp < LL) {
        float s = 0.f;
        for (int c = lane; c < CTOT; c += 32) s += conv_w[warp * CTOT + c];
        #pragma unroll
        for (int off = 16; off; off >>= 1) s += __shfl_down_sync(0xffffffffu, s, off);
        if (lane == 0) g_asq[warp] = s;
    }
}

// ---------------------------------------------------------------------------
// Partial ab from l4 on native 14x14 grid.
// grid: (13, 8)  block: 256.  pair index over 32 batches * 98 pixel-pairs.
__global__ void k_ab4(const float* __restrict__ l4, const float* __restrict__ conv_w) {
    __shared__ __align__(16) float w_s[LL * 256];
    int ck = blockIdx.y;  // channel chunk (256 channels each), channels [ck*256, ...)
    for (int i = threadIdx.x; i < LL * 256; i += 256) {
        int l = i >> 8, ci = i & 255;
        w_s[l * 256 + ci] = conv_w[l * CTOT + ck * 256 + ci];
    }
    __syncthreads();

    int g = blockIdx.x * 256 + threadIdx.x;
    if (g >= BB * (HW4 / 2)) return;
    int b = g / (HW4 / 2);
    int q = (g % (HW4 / 2)) * 2;

    const float* src = l4 + ((size_t)b * C4 + (size_t)ck * 256) * HW4 + q;

    float2 acc[LL];
    #pragma unroll
    for (int l = 0; l < LL; l++) acc[l] = make_float2(0.f, 0.f);

    #pragma unroll 4
    for (int ci = 0; ci < 256; ci += 2) {
        float2 xa = *(const float2*)(src + (size_t)ci * HW4);
        float2 xb = *(const float2*)(src + (size_t)(ci + 1) * HW4);
        #pragma unroll
        for (int l = 0; l < LL; l++) {
            float2 w = *(const float2*)&w_s[l * 256 + ci];
            acc[l].x = fmaf(w.x, xa.x, acc[l].x);
            acc[l].x = fmaf(w.y, xb.x, acc[l].x);
            acc[l].y = fmaf(w.x, xa.y, acc[l].y);
            acc[l].y = fmaf(w.y, xb.y, acc[l].y);
        }
    }
    #pragma unroll
    for (int l = 0; l < LL; l++)
        *(float2*)&g_pab4[((size_t)(ck * BB + b) * LL + l) * HW4 + q] = acc[l];
}

// ---------------------------------------------------------------------------
// Partial ab from l3 on 28x28 grid.
// grid: (49, 4)  block: 256.  pair index over 32 batches * 392 pixel-pairs (exact).
__global__ void k_ab3(const float* __restrict__ l3, const float* __restrict__ conv_w) {
    __shared__ __align__(16) float w_s[LL * 256];
    int ck = blockIdx.y;  // channels [C4 + ck*256, ...)
    for (int i = threadIdx.x; i < LL * 256; i += 256) {
        int l = i >> 8, ci = i & 255;
        w_s[l * 256 + ci] = conv_w[l * CTOT + C4 + ck * 256 + ci];
    }
    __syncthreads();

    int g = blockIdx.x * 256 + threadIdx.x;   // 0 .. 12543
    int b = g / (HW / 2);
    int p = (g % (HW / 2)) * 2;

    const float* src = l3 + ((size_t)b * C3 + (size_t)ck * 256) * HW + p;

    float2 acc[LL];
    #pragma unroll
    for (int l = 0; l < LL; l++) acc[l] = make_float2(0.f, 0.f);

    #pragma unroll 4
    for (int ci = 0; ci < 256; ci += 2) {
        float2 xa = *(const float2*)(src + (size_t)ci * HW);
        float2 xb = *(const float2*)(src + (size_t)(ci + 1) * HW);
        #pragma unroll
        for (int l = 0; l < LL; l++) {
            float2 w = *(const float2*)&w_s[l * 256 + ci];
            acc[l].x = fmaf(w.x, xa.x, acc[l].x);
            acc[l].x = fmaf(w.y, xb.x, acc[l].x);
            acc[l].y = fmaf(w.x, xa.y, acc[l].y);
            acc[l].y = fmaf(w.y, xb.y, acc[l].y);
        }
    }
    #pragma unroll
    for (int l = 0; l < LL; l++)
        *(float2*)&g_pab3[((size_t)(ck * BB + b) * LL + l) * HW + p] = acc[l];
}

// ---------------------------------------------------------------------------
// Reduce l4 chunk partials: g_ab4[i] = sum_ck g_pab4[ck][i]
__global__ void k_red4() {
    int i = blockIdx.x * 256 + threadIdx.x;
    if (i >= BB * LL * HW4) return;
    float s = 0.f;
    #pragma unroll
    for (int ck = 0; ck < 8; ck++) s += g_pab4[(size_t)ck * (BB * LL * HW4) + i];
    g_ab4[i] = s;
}

// ---------------------------------------------------------------------------
// Per-pixel: gather l3 partials, bilinear-upsample l4 ab, softmax over L.
// b_sq dropped (constant over softmax axis). grid 98, block 256 (exact 25088).
__global__ void k_softmax(float* __restrict__ maps_out) {
    int t = blockIdx.x * 256 + threadIdx.x;
    int b = t / HW, p = t % HW;
    int y = p / HH, x = p % HH;

    float fy = y * 0.5f - 0.25f;
    int iy = (int)floorf(fy);
    float wy1 = fy - (float)iy;
    float wy0 = 1.f - wy1;
    int y0 = max(iy, 0), y1 = min(iy + 1, H4 - 1);

    float fx = x * 0.5f - 0.25f;
    int ix = (int)floorf(fx);
    float wx1 = fx - (float)ix;
    float wx0 = 1.f - wx1;
    int x0 = max(ix, 0), x1 = min(ix + 1, H4 - 1);

    float logit[LL];
    float mx = -1e30f;
    #pragma unroll
    for (int l = 0; l < LL; l++) {
        const float* a4 = g_ab4 + (size_t)(b * LL + l) * HW4;
        float v = wy0 * (wx0 * a4[y0 * H4 + x0] + wx1 * a4[y0 * H4 + x1])
                + wy1 * (wx0 * a4[y1 * H4 + x0] + wx1 * a4[y1 * H4 + x1]);
        float s3 = 0.f;
        #pragma unroll
        for (int ck = 0; ck < 4; ck++)
            s3 += g_pab3[((size_t)(ck * BB + b) * LL + l) * HW + p];
        float lg = 2.f * (v + s3) - g_asq[l];
        logit[l] = lg;
        mx = fmaxf(mx, lg);
    }
    float e[LL], den = 0.f;
    #pragma unroll
    for (int l = 0; l < LL; l++) { e[l] = expf(logit[l] - mx); den += e[l]; }
    float inv = 1.f / den;
    #pragma unroll
    for (int l = 0; l < LL; l++)
        maps_out[(size_t)(b * LL + l) * HW + p] = e[l] * inv;
}

// ---------------------------------------------------------------------------
// Adjoint bilinear weight: contribution of output index y to input index r.
__device__ __forceinline__ float tapw(int y, int r) {
    float f = y * 0.5f - 0.25f;
    int i0 = (int)floorf(f);
    float w1 = f - (float)i0;
    int c0 = max(i0, 0), c1 = min(i0 + 1, H4 - 1);
    float w = 0.f;
    if (c0 == r) w += 1.f - w1;
    if (c1 == r) w += w1;
    return w;
}

// maps_down[b][l][q] = sum_p coef(p,q) * maps[b][l][p]
__global__ void k_mdown(const float* __restrict__ maps_out) {
    int t = blockIdx.x * 256 + threadIdx.x;
    if (t >= BB * LL * HW4) return;
    int q = t % HW4;
    int l = (t / HW4) % LL;
    int b = t / (HW4 * LL);
    int r = q / H4, c = q % H4;
    const float* mp = maps_out + (size_t)(b * LL + l) * HW;

    int ylo = max(0, 2 * r - 1), yhi = min(HH - 1, 2 * r + 2);
    int xlo = max(0, 2 * c - 1), xhi = min(HH - 1, 2 * c + 2);
    float s = 0.f;
    for (int y = ylo; y <= yhi; y++) {
        float wy = tapw(y, r);
        for (int x = xlo; x <= xhi; x++)
            s += wy * tapw(x, c) * mp[y * HH + x];
    }
    g_mdown[t] = s;
}

// ---------------------------------------------------------------------------
// all_features for l4 channels (c < 2048) via adjoint maps on 14x14.
// grid (32 ctiles, 32 b), block 256. warp handles 8 channels.
__global__ void k_feat4(const float* __restrict__ l4, const float* __restrict__ modulation,
                        float* __restrict__ af_out) {
    __shared__ float md_s[LL * HW4];
    int b = blockIdx.y;
    int ct = blockIdx.x;
    for (int i = threadIdx.x; i < LL * HW4; i += 256)
        md_s[i] = g_mdown[(size_t)b * LL * HW4 + i];
    __syncthreads();

    int warp = threadIdx.x >> 5, lane = threadIdx.x & 31;
    for (int cc = 0; cc < 8; cc++) {
        int c = ct * 64 + warp * 8 + cc;
        const float* src = l4 + ((size_t)b * C4 + c) * HW4;
        float acc[LL];
        #pragma unroll
        for (int l = 0; l < LL; l++) acc[l] = 0.f;
        for (int q = lane; q < HW4; q += 32) {
            float xv = src[q];
            #pragma unroll
            for (int l = 0; l < LL; l++) acc[l] = fmaf(md_s[l * HW4 + q], xv, acc[l]);
        }
        #pragma unroll
        for (int l = 0; l < LL; l++)
            #pragma unroll
            for (int off = 16; off; off >>= 1)
                acc[l] += __shfl_down_sync(0xffffffffu, acc[l], off);
        if (lane == 0) {
            float mf = 0.f;
            #pragma unroll
            for (int l = 0; l < LL; l++) {
                float v = acc[l] * (1.f / (float)HW);
                af_out[((size_t)b * CTOT + c) * LL + l] = v;
                if (l < LL - 1) mf = fmaf(v, modulation[c * LL + l], mf);
            }
            g_meanf[(size_t)b * CTOT + c] = mf * (1.f / 8.f);
        }
    }
}

// all_features for l3 channels (c >= 2048) with full-res maps.
// grid (16 ctiles, 32 b), block 256.
__global__ void k_feat3(const float* __restrict__ l3, const float* __restrict__ maps_out,
                        const float* __restrict__ modulation, float* __restrict__ af_out) {
    __shared__ float mp_s[LL * HW];   // 28224 B
    int b = blockIdx.y;
    int ct = blockIdx.x;
    for (int i = threadIdx.x; i < LL * HW; i += 256)
        mp_s[i] = maps_out[(size_t)b * LL * HW + i];
    __syncthreads();

    int warp = threadIdx.x >> 5, lane = threadIdx.x & 31;
    for (int cc = 0; cc < 8; cc++) {
        int cl = ct * 64 + warp * 8 + cc;      // 0..1023
        int c = C4 + cl;
        const float* src = l3 + ((size_t)b * C3 + cl) * HW;
        float acc[LL];
        #pragma unroll
        for (int l = 0; l < LL; l++) acc[l] = 0.f;
        for (int p = lane; p < HW; p += 32) {
            float xv = src[p];
            #pragma unroll
            for (int l = 0; l < LL; l++) acc[l] = fmaf(mp_s[l * HW + p], xv, acc[l]);
        }
        #pragma unroll
        for (int l = 0; l < LL; l++)
            #pragma unroll
            for (int off = 16; off; off >>= 1)
                acc[l] += __shfl_down_sync(0xffffffffu, acc[l], off);
        if (lane == 0) {
            float mf = 0.f;
            #pragma unroll
            for (int l = 0; l < LL; l++) {
                float v = acc[l] * (1.f / (float)HW);
                af_out[((size_t)b * CTOT + c) * LL + l] = v;
                if (l < LL - 1) mf = fmaf(v, modulation[c * LL + l], mf);
            }
            g_meanf[(size_t)b * CTOT + c] = mf * (1.f / 8.f);
        }
    }
}

// ---------------------------------------------------------------------------
// attr_scores = mean_features @ attr_w^T + attr_b.
// grid 312 blocks (one per attribute), 4 warps; each warp covers 8 batches.
__global__ void k_attr(const float* __restrict__ attr_w, const float* __restrict__ attr_b,
                       float* __restrict__ attr_out) {
    int a = blockIdx.x;
    int warp = threadIdx.x >> 5, lane = threadIdx.x & 31;
    const float* wrow = attr_w + (size_t)a * CTOT;
    float acc[8];
    #pragma unroll
    for (int j = 0; j < 8; j++) acc[j] = 0.f;
    for (int k = lane; k < CTOT; k += 32) {
        float wv = wrow[k];
        #pragma unroll
        for (int j = 0; j < 8; j++)
            acc[j] = fmaf(wv, g_meanf[(size_t)(warp * 8 + j) * CTOT + k], acc[j]);
    }
    #pragma unroll
    for (int j = 0; j < 8; j++)
        #pragma unroll
        for (int off = 16; off; off >>= 1)
            acc[j] += __shfl_down_sync(0xffffffffu, acc[j], off);
    if (lane == 0) {
        float bias = attr_b[a];
        #pragma unroll
        for (int j = 0; j < 8; j++)
            attr_out[(size_t)(warp * 8 + j) * NA + a] = acc[j] + bias;
    }
}

// class_scores = attr_scores @ class_w^T
__global__ void k_class(const float* __restrict__ attr_out, const float* __restrict__ class_w,
                        float* __restrict__ class_out) {
    int t = blockIdx.x * 256 + threadIdx.x;
    if (t >= BB * NC) return;
    int b = t / NC, nc = t % NC;
    const float* ar = attr_out + (size_t)b * NA;
    const float* wr = class_w + (size_t)nc * NA;
    float s = 0.f;
    #pragma unroll 4
    for (int k = 0; k < NA; k++) s = fmaf(ar[k], wr[k], s);
    class_out[t] = s;
}

// ---------------------------------------------------------------------------
extern "C" void kernel_launch(void* const* d_in, const int* in_sizes, int n_in,
                              void* d_out, int out_size) {
    const float* l3     = (const float*)d_in[0];
    const float* l4     = (const float*)d_in[1];
    const float* conv_w = (const float*)d_in[2];
    const float* modu   = (const float*)d_in[3];
    const float* attr_w = (const float*)d_in[4];
    const float* attr_b = (const float*)d_in[5];
    const float* class_w= (const float*)d_in[6];

    float* out = (float*)d_out;
    float* attr_out  = out + OFF_ATTR;
    float* class_out = out + OFF_CLASS;
    float* maps_out  = out + OFF_MAPS;
    float* af_out    = out + OFF_AF;

    k_prep<<<1, 288>>>(conv_w);
    k_ab4<<<dim3(13, 8), 256>>>(l4, conv_w);
    k_ab3<<<dim3(49, 4), 256>>>(l3, conv_w);
    k_red4<<<(BB * LL * HW4 + 255) / 256, 256>>>();
    k_softmax<<<98, 256>>>(maps_out);
    k_mdown<<<(BB * LL * HW4 + 255) / 256, 256>>>(maps_out);
    k_feat4<<<dim3(32, BB), 256>>>(l4, modu, af_out);
    k_feat3<<<dim3(16, BB), 256>>>(l3, maps_out, modu, af_out);
    k_attr<<<NA, 128>>>(attr_w, attr_b, attr_out);
    k_class<<<(BB * NC + 255) / 256, 256>>>(attr_out, class_w, class_out);
}

// round 3
// speedup vs baseline: 1.2383x; 1.2383x over previous
#include <cuda_runtime.h>
#include <math.h>

// Problem constants
#define BB 32
#define C3 1024
#define C4 2048
#define CTOT 3072
#define HH 28
#define HW 784
#define H4 14
#define HW4 196
#define LL 9
#define NA 312
#define NC 200

#define NCH3 8      // l3 channel chunks of 128
#define NCH4 16     // l4 channel chunks of 128

// Output layout (flattened concat of reference return tuple)
#define OFF_ATTR  0
#define OFF_CLASS (BB*NA)                  // 9984
#define OFF_MAPS  (OFF_CLASS + BB*NC)      // 16384
#define OFF_AF    (OFF_MAPS + BB*LL*HW)    // 242176

// Scratch (__device__ globals; no runtime allocation allowed)
__device__ __align__(16) float g_pab4[NCH4 * BB * LL * HW4];  // l4 partial ab, 14x14
__device__ __align__(16) float g_pab3[NCH3 * BB * LL * HW];   // l3 partial ab, 28x28
__device__ __align__(16) float g_ab4[BB * LL * HW4];          // reduced l4 ab
__device__ __align__(16) float g_mdown[BB * LL * HW4];        // adjoint-downsampled maps
__device__ __align__(16) float g_meanf[BB * CTOT];            // mean features
__device__ float g_asq[LL];

// ---------------------------------------------------------------------------
// a_sq[l] = sum_c conv_w[l][c]
__global__ void k_prep(const float* __restrict__ conv_w) {
    int warp = threadIdx.x >> 5, lane = threadIdx.x & 31;
    if (warp < LL) {
        float s = 0.f;
        for (int c = lane; c < CTOT; c += 32) s += conv_w[warp * CTOT + c];
        #pragma unroll
        for (int off = 16; off; off >>= 1) s += __shfl_down_sync(0xffffffffu, s, off);
        if (lane == 0) g_asq[warp] = s;
    }
}

// ---------------------------------------------------------------------------
// Partial ab from l4 on native 14x14 grid. 128-ch chunks, 2-pixel threads.
// grid (14, 16), block 224. 14*224 = 3136 = 32 b * 98 px-pairs exactly.
__global__ void __launch_bounds__(224) k_ab4(const float* __restrict__ l4,
                                             const float* __restrict__ conv_w) {
    __shared__ __align__(16) float w_s[LL * 128];
    int ck = blockIdx.y;
    for (int i = threadIdx.x; i < LL * 128; i += 224) {
        int l = i >> 7, ci = i & 127;
        w_s[l * 128 + ci] = conv_w[l * CTOT + ck * 128 + ci];
    }
    __syncthreads();

    int g = blockIdx.x * 224 + threadIdx.x;   // 0..3135
    int b = g / 98;
    int q = (g % 98) * 2;

    const float* src = l4 + ((size_t)b * C4 + (size_t)ck * 128) * HW4 + q;

    float2 acc[LL];
    #pragma unroll
    for (int l = 0; l < LL; l++) acc[l] = make_float2(0.f, 0.f);

    #pragma unroll 4
    for (int ci = 0; ci < 128; ci += 2) {
        float2 xa = *(const float2*)(src + (size_t)ci * HW4);
        float2 xb = *(const float2*)(src + (size_t)(ci + 1) * HW4);
        #pragma unroll
        for (int l = 0; l < LL; l++) {
            float2 w = *(const float2*)&w_s[l * 128 + ci];
            acc[l].x = fmaf(w.x, xa.x, acc[l].x);
            acc[l].x = fmaf(w.y, xb.x, acc[l].x);
            acc[l].y = fmaf(w.x, xa.y, acc[l].y);
            acc[l].y = fmaf(w.y, xb.y, acc[l].y);
        }
    }
    #pragma unroll
    for (int l = 0; l < LL; l++)
        *(float2*)&g_pab4[((size_t)(ck * BB + b) * LL + l) * HW4 + q] = acc[l];
}

// ---------------------------------------------------------------------------
// Partial ab from l3 on 28x28 grid. 128-ch chunks, 4-pixel (float4) threads.
// grid (28, 8), block 224. 28*224 = 6272 = 32 b * 196 px-quads exactly.
__global__ void __launch_bounds__(224) k_ab3(const float* __restrict__ l3,
                                             const float* __restrict__ conv_w) {
    __shared__ __align__(16) float w_s[LL * 128];
    int ck = blockIdx.y;
    for (int i = threadIdx.x; i < LL * 128; i += 224) {
        int l = i >> 7, ci = i & 127;
        w_s[l * 128 + ci] = conv_w[l * CTOT + C4 + ck * 128 + ci];
    }
    __syncthreads();

    int g = blockIdx.x * 224 + threadIdx.x;   // 0..6271
    int b = g / 196;
    int p = (g % 196) * 4;

    const float* src = l3 + ((size_t)b * C3 + (size_t)ck * 128) * HW + p;

    float4 acc[LL];
    #pragma unroll
    for (int l = 0; l < LL; l++) acc[l] = make_float4(0.f, 0.f, 0.f, 0.f);

    #pragma unroll 2
    for (int ci = 0; ci < 128; ci += 2) {
        float4 xa = *(const float4*)(src + (size_t)ci * HW);
        float4 xb = *(const float4*)(src + (size_t)(ci + 1) * HW);
        #pragma unroll
        for (int l = 0; l < LL; l++) {
            float2 w = *(const float2*)&w_s[l * 128 + ci];
            acc[l].x = fmaf(w.x, xa.x, acc[l].x);
            acc[l].x = fmaf(w.y, xb.x, acc[l].x);
            acc[l].y = fmaf(w.x, xa.y, acc[l].y);
            acc[l].y = fmaf(w.y, xb.y, acc[l].y);
            acc[l].z = fmaf(w.x, xa.z, acc[l].z);
            acc[l].z = fmaf(w.y, xb.z, acc[l].z);
            acc[l].w = fmaf(w.x, xa.w, acc[l].w);
            acc[l].w = fmaf(w.y, xb.w, acc[l].w);
        }
    }
    #pragma unroll
    for (int l = 0; l < LL; l++)
        *(float4*)&g_pab3[((size_t)(ck * BB + b) * LL + l) * HW + p] = acc[l];
}

// ---------------------------------------------------------------------------
// Reduce l4 chunk partials (float4 vectorized): g_ab4 = sum_ck g_pab4[ck]
__global__ void k_red4() {
    int t = blockIdx.x * 256 + threadIdx.x;
    if (t >= BB * LL * HW4 / 4) return;
    const float4* src = (const float4*)g_pab4;
    float4 s = make_float4(0.f, 0.f, 0.f, 0.f);
    #pragma unroll
    for (int ck = 0; ck < NCH4; ck++) {
        float4 v = src[(size_t)ck * (BB * LL * HW4 / 4) + t];
        s.x += v.x; s.y += v.y; s.z += v.z; s.w += v.w;
    }
    ((float4*)g_ab4)[t] = s;
}

// ---------------------------------------------------------------------------
// Per-pixel: gather l3 partials, bilinear-upsample l4 ab, softmax over L.
// b_sq dropped (constant over softmax axis). grid 98, block 256 (exact 25088).
__global__ void k_softmax(float* __restrict__ maps_out) {
    int t = blockIdx.x * 256 + threadIdx.x;
    int b = t / HW, p = t % HW;
    int y = p / HH, x = p % HH;

    float fy = y * 0.5f - 0.25f;
    int iy = (int)floorf(fy);
    float wy1 = fy - (float)iy;
    float wy0 = 1.f - wy1;
    int y0 = max(iy, 0), y1 = min(iy + 1, H4 - 1);

    float fx = x * 0.5f - 0.25f;
    int ix = (int)floorf(fx);
    float wx1 = fx - (float)ix;
    float wx0 = 1.f - wx1;
    int x0 = max(ix, 0), x1 = min(ix + 1, H4 - 1);

    float logit[LL];
    float mx = -1e30f;
    #pragma unroll
    for (int l = 0; l < LL; l++) {
        const float* a4 = g_ab4 + (size_t)(b * LL + l) * HW4;
        float v = wy0 * (wx0 * a4[y0 * H4 + x0] + wx1 * a4[y0 * H4 + x1])
                + wy1 * (wx0 * a4[y1 * H4 + x0] + wx1 * a4[y1 * H4 + x1]);
        float s3 = 0.f;
        #pragma unroll
        for (int ck = 0; ck < NCH3; ck++)
            s3 += g_pab3[((size_t)(ck * BB + b) * LL + l) * HW + p];
        float lg = 2.f * (v + s3) - g_asq[l];
        logit[l] = lg;
        mx = fmaxf(mx, lg);
    }
    float e[LL], den = 0.f;
    #pragma unroll
    for (int l = 0; l < LL; l++) { e[l] = __expf(logit[l] - mx); den += e[l]; }
    float inv = 1.f / den;
    #pragma unroll
    for (int l = 0; l < LL; l++)
        maps_out[(size_t)(b * LL + l) * HW + p] = e[l] * inv;
}

// ---------------------------------------------------------------------------
// Adjoint bilinear weight: contribution of output index y to input index r.
__device__ __forceinline__ float tapw(int y, int r) {
    float f = y * 0.5f - 0.25f;
    int i0 = (int)floorf(f);
    float w1 = f - (float)i0;
    int c0 = max(i0, 0), c1 = min(i0 + 1, H4 - 1);
    float w = 0.f;
    if (c0 == r) w += 1.f - w1;
    if (c1 == r) w += w1;
    return w;
}

// maps_down[b][l][q] = sum_p coef(p,q) * maps[b][l][p]
__global__ void k_mdown(const float* __restrict__ maps_out) {
    int t = blockIdx.x * 256 + threadIdx.x;
    if (t >= BB * LL * HW4) return;
    int q = t % HW4;
    int l = (t / HW4) % LL;
    int b = t / (HW4 * LL);
    int r = q / H4, c = q % H4;
    const float* mp = maps_out + (size_t)(b * LL + l) * HW;

    int ylo = max(0, 2 * r - 1), yhi = min(HH - 1, 2 * r + 2);
    int xlo = max(0, 2 * c - 1), xhi = min(HH - 1, 2 * c + 2);
    float s = 0.f;
    for (int y = ylo; y <= yhi; y++) {
        float wy = tapw(y, r);
        for (int x = xlo; x <= xhi; x++)
            s += wy * tapw(x, c) * mp[y * HH + x];
    }
    g_mdown[t] = s;
}

// ---------------------------------------------------------------------------
// all_features for l3 channels (c >= 2048), 8-channel register tiling.
// Each warp owns 8 channels; lanes stride pixels. grid (16, 32), block 256.
__global__ void __launch_bounds__(256, 2)
k_feat3(const float* __restrict__ l3, const float* __restrict__ maps_out,
        const float* __restrict__ modulation, float* __restrict__ af_out) {
    __shared__ float mp_s[LL * HW];   // 28224 B
    int b = blockIdx.y;
    int ct = blockIdx.x;
    for (int i = threadIdx.x; i < LL * HW; i += 256)
        mp_s[i] = maps_out[(size_t)b * LL * HW + i];
    __syncthreads();

    int warp = threadIdx.x >> 5, lane = threadIdx.x & 31;
    int c0 = ct * 64 + warp * 8;                 // local channel base (0..1016)
    const float* base = l3 + ((size_t)b * C3 + c0) * HW;

    float acc[8][LL];
    #pragma unroll
    for (int cc = 0; cc < 8; cc++)
        #pragma unroll
        for (int l = 0; l < LL; l++) acc[cc][l] = 0.f;

    // 24 full iterations (768 pixels)
    for (int p0 = 0; p0 < 768; p0 += 32) {
        int p = p0 + lane;
        float m[LL];
        #pragma unroll
        for (int l = 0; l < LL; l++) m[l] = mp_s[l * HW + p];
        #pragma unroll
        for (int cc = 0; cc < 8; cc++) {
            float xv = base[(size_t)cc * HW + p];
            #pragma unroll
            for (int l = 0; l < LL; l++) acc[cc][l] = fmaf(m[l], xv, acc[cc][l]);
        }
    }
    // tail: 16 pixels
    {
        int p = 768 + lane;
        bool ok = p < HW;
        float m[LL];
        #pragma unroll
        for (int l = 0; l < LL; l++) m[l] = ok ? mp_s[l * HW + p] : 0.f;
        #pragma unroll
        for (int cc = 0; cc < 8; cc++) {
            float xv = ok ? base[(size_t)cc * HW + p] : 0.f;
            #pragma unroll
            for (int l = 0; l < LL; l++) acc[cc][l] = fmaf(m[l], xv, acc[cc][l]);
        }
    }

    // butterfly reduce across lanes (all lanes end with full sums)
    #pragma unroll
    for (int off = 16; off; off >>= 1)
        #pragma unroll
        for (int cc = 0; cc < 8; cc++)
            #pragma unroll
            for (int l = 0; l < LL; l++)
                acc[cc][l] += __shfl_xor_sync(0xffffffffu, acc[cc][l], off);

    if (lane < 8) {
        int cc = lane;
        int c = C4 + c0 + cc;
        float mf = 0.f;
        #pragma unroll
        for (int l = 0; l < LL; l++) {
            float v = acc[cc][l] * (1.f / (float)HW);
            af_out[((size_t)b * CTOT + c) * LL + l] = v;
            if (l < LL - 1) mf = fmaf(v, modulation[c * LL + l], mf);
        }
        g_meanf[(size_t)b * CTOT + c] = mf * (1.f / 8.f);
    }
}

// all_features for l4 channels (c < 2048) via adjoint maps on 14x14.
// 8-channel register tiling. grid (32, 32), block 256.
__global__ void __launch_bounds__(256, 2)
k_feat4(const float* __restrict__ l4, const float* __restrict__ modulation,
        float* __restrict__ af_out) {
    __shared__ float md_s[LL * HW4];
    int b = blockIdx.y;
    int ct = blockIdx.x;
    for (int i = threadIdx.x; i < LL * HW4; i += 256)
        md_s[i] = g_mdown[(size_t)b * LL * HW4 + i];
    __syncthreads();

    int warp = threadIdx.x >> 5, lane = threadIdx.x & 31;
    int c0 = ct * 64 + warp * 8;                 // 0..2040
    const float* base = l4 + ((size_t)b * C4 + c0) * HW4;

    float acc[8][LL];
    #pragma unroll
    for (int cc = 0; cc < 8; cc++)
        #pragma unroll
        for (int l = 0; l < LL; l++) acc[cc][l] = 0.f;

    // 6 full iterations (192 pixels)
    for (int p0 = 0; p0 < 192; p0 += 32) {
        int p = p0 + lane;
        float m[LL];
        #pragma unroll
        for (int l = 0; l < LL; l++) m[l] = md_s[l * HW4 + p];
        #pragma unroll
        for (int cc = 0; cc < 8; cc++) {
            float xv = base[(size_t)cc * HW4 + p];
            #pragma unroll
            for (int l = 0; l < LL; l++) acc[cc][l] = fmaf(m[l], xv, acc[cc][l]);
        }
    }
    // tail: 4 pixels
    {
        int p = 192 + lane;
        bool ok = p < HW4;
        float m[LL];
        #pragma unroll
        for (int l = 0; l < LL; l++) m[l] = ok ? md_s[l * HW4 + p] : 0.f;
        #pragma unroll
        for (int cc = 0; cc < 8; cc++) {
            float xv = ok ? base[(size_t)cc * HW4 + p] : 0.f;
            #pragma unroll
            for (int l = 0; l < LL; l++) acc[cc][l] = fmaf(m[l], xv, acc[cc][l]);
        }
    }

    #pragma unroll
    for (int off = 16; off; off >>= 1)
        #pragma unroll
        for (int cc = 0; cc < 8; cc++)
            #pragma unroll
            for (int l = 0; l < LL; l++)
                acc[cc][l] += __shfl_xor_sync(0xffffffffu, acc[cc][l], off);

    if (lane < 8) {
        int cc = lane;
        int c = c0 + cc;
        float mf = 0.f;
        #pragma unroll
        for (int l = 0; l < LL; l++) {
            float v = acc[cc][l] * (1.f / (float)HW);
            af_out[((size_t)b * CTOT + c) * LL + l] = v;
            if (l < LL - 1) mf = fmaf(v, modulation[c * LL + l], mf);
        }
        g_meanf[(size_t)b * CTOT + c] = mf * (1.f / 8.f);
    }
}

// ---------------------------------------------------------------------------
// attr_scores = mean_features @ attr_w^T + attr_b.
// grid 312 blocks (one per attribute), 4 warps; each warp covers 8 batches.
__global__ void k_attr(const float* __restrict__ attr_w, const float* __restrict__ attr_b,
                       float* __restrict__ attr_out) {
    int a = blockIdx.x;
    int warp = threadIdx.x >> 5, lane = threadIdx.x & 31;
    const float* wrow = attr_w + (size_t)a * CTOT;
    float acc[8];
    #pragma unroll
    for (int j = 0; j < 8; j++) acc[j] = 0.f;
    for (int k = lane; k < CTOT; k += 32) {
        float wv = wrow[k];
        #pragma unroll
        for (int j = 0; j < 8; j++)
            acc[j] = fmaf(wv, g_meanf[(size_t)(warp * 8 + j) * CTOT + k], acc[j]);
    }
    #pragma unroll
    for (int j = 0; j < 8; j++)
        #pragma unroll
        for (int off = 16; off; off >>= 1)
            acc[j] += __shfl_down_sync(0xffffffffu, acc[j], off);
    if (lane == 0) {
        float bias = attr_b[a];
        #pragma unroll
        for (int j = 0; j < 8; j++)
            attr_out[(size_t)(warp * 8 + j) * NA + a] = acc[j] + bias;
    }
}

// class_scores = attr_scores @ class_w^T
__global__ void k_class(const float* __restrict__ attr_out, const float* __restrict__ class_w,
                        float* __restrict__ class_out) {
    int t = blockIdx.x * 256 + threadIdx.x;
    if (t >= BB * NC) return;
    int b = t / NC, nc = t % NC;
    const float* ar = attr_out + (size_t)b * NA;
    const float* wr = class_w + (size_t)nc * NA;
    float s = 0.f;
    #pragma unroll 4
    for (int k = 0; k < NA; k++) s = fmaf(ar[k], wr[k], s);
    class_out[t] = s;
}

// ---------------------------------------------------------------------------
extern "C" void kernel_launch(void* const* d_in, const int* in_sizes, int n_in,
                              void* d_out, int out_size) {
    const float* l3     = (const float*)d_in[0];
    const float* l4     = (const float*)d_in[1];
    const float* conv_w = (const float*)d_in[2];
    const float* modu   = (const float*)d_in[3];
    const float* attr_w = (const float*)d_in[4];
    const float* attr_b = (const float*)d_in[5];
    const float* class_w= (const float*)d_in[6];

    float* out = (float*)d_out;
    float* attr_out  = out + OFF_ATTR;
    float* class_out = out + OFF_CLASS;
    float* maps_out  = out + OFF_MAPS;
    float* af_out    = out + OFF_AF;

    // Order chosen so heavy kernels land in ncu's capture slots:
    // #4 = k_ab3, #6 = k_feat3.
    k_prep<<<1, 288>>>(conv_w);
    k_ab4<<<dim3(14, NCH4), 224>>>(l4, conv_w);
    k_red4<<<(BB * LL * HW4 / 4 + 255) / 256, 256>>>();
    k_ab3<<<dim3(28, NCH3), 224>>>(l3, conv_w);
    k_softmax<<<98, 256>>>(maps_out);
    k_feat3<<<dim3(16, BB), 256>>>(l3, maps_out, modu, af_out);
    k_mdown<<<(BB * LL * HW4 + 255) / 256, 256>>>(maps_out);
    k_feat4<<<dim3(32, BB), 256>>>(l4, modu, af_out);
    k_attr<<<NA, 128>>>(attr_w, attr_b, attr_out);
    k_class<<<(BB * NC + 255) / 256, 256>>>(attr_out, class_w, class_out);
}

// round 7
// speedup vs baseline: 1.4336x; 1.1577x over previous
#include <cuda_runtime.h>
#include <math.h>

// Problem constants
#define BB 32
#define C3 1024
#define C4 2048
#define CTOT 3072
#define HH 28
#define HW 784
#define H4 14
#define HW4 196
#define LL 9
#define NA 312
#define NC 200

#define NCH3 16     // l3 channel chunks of 64
#define NCH4 32     // l4 channel chunks of 64
#define RED4_N (BB * LL * HW4 / 4)   // 14112 float4 elems

// Output layout (flattened concat of reference return tuple)
#define OFF_ATTR  0
#define OFF_CLASS (BB*NA)                  // 9984
#define OFF_MAPS  (OFF_CLASS + BB*NC)      // 16384
#define OFF_AF    (OFF_MAPS + BB*LL*HW)    // 242176

// Scratch (__device__ globals; no runtime allocation allowed)
__device__ __align__(16) float g_pab4[NCH4 * BB * LL * HW4];  // l4 partial ab, 14x14
__device__ __align__(16) float g_pab3[NCH3 * BB * LL * HW];   // l3 partial ab, 28x28
__device__ __align__(16) float g_ab4[BB * LL * HW4];          // reduced l4 ab
__device__ __align__(16) float g_mdown[BB * LL * HW4];        // adjoint-downsampled maps
__device__ __align__(16) float g_meanf[BB * CTOT];            // mean features
__device__ float g_asq[LL];

// ---------------------------------------------------------------------------
// Partial ab from l4 on native 14x14 grid. 64-ch chunks, 2-pixel threads.
// grid (14, 32), block 224. 14*224 = 3136 = 32 b * 98 px-pairs exactly.
__global__ void __launch_bounds__(224) k_ab4(const float* __restrict__ l4,
                                             const float* __restrict__ conv_w) {
    __shared__ __align__(16) float w_s[LL * 64];
    int ck = blockIdx.y;
    for (int i = threadIdx.x; i < LL * 64; i += 224)
        w_s[i] = conv_w[(i / 64) * CTOT + ck * 64 + (i & 63)];
    __syncthreads();

    int g = blockIdx.x * 224 + threadIdx.x;   // 0..3135
    int b = g / 98;
    int q = (g % 98) * 2;

    const float* src = l4 + ((size_t)b * C4 + (size_t)ck * 64) * HW4 + q;

    float2 acc[LL];
    #pragma unroll
    for (int l = 0; l < LL; l++) acc[l] = make_float2(0.f, 0.f);

    #pragma unroll 2
    for (int ci = 0; ci < 64; ci += 4) {
        float2 x0 = *(const float2*)(src + (size_t)(ci + 0) * HW4);
        float2 x1 = *(const float2*)(src + (size_t)(ci + 1) * HW4);
        float2 x2 = *(const float2*)(src + (size_t)(ci + 2) * HW4);
        float2 x3 = *(const float2*)(src + (size_t)(ci + 3) * HW4);
        #pragma unroll
        for (int l = 0; l < LL; l++) {
            float4 w = *(const float4*)&w_s[l * 64 + ci];
            acc[l].x = fmaf(w.x, x0.x, acc[l].x);
            acc[l].y = fmaf(w.x, x0.y, acc[l].y);
            acc[l].x = fmaf(w.y, x1.x, acc[l].x);
            acc[l].y = fmaf(w.y, x1.y, acc[l].y);
            acc[l].x = fmaf(w.z, x2.x, acc[l].x);
            acc[l].y = fmaf(w.z, x2.y, acc[l].y);
            acc[l].x = fmaf(w.w, x3.x, acc[l].x);
            acc[l].y = fmaf(w.w, x3.y, acc[l].y);
        }
    }
    #pragma unroll
    for (int l = 0; l < LL; l++)
        *(float2*)&g_pab4[((size_t)(ck * BB + b) * LL + l) * HW4 + q] = acc[l];
}

// ---------------------------------------------------------------------------
// Partial ab from l3 on 28x28 grid. 64-ch chunks, 4-pixel (float4) threads.
// grid (30, 16): x<28 main work (28*224 = 6272 = 32 b * 196 quads);
// x>=28: 32 extra blocks do the g_pab4 reduction (red4) + asq prep.
__global__ void __launch_bounds__(224) k_ab3(const float* __restrict__ l3,
                                             const float* __restrict__ conv_w) {
    __shared__ __align__(16) float s_buf[LL * 224];   // w_s uses first LL*64
    int tid = threadIdx.x;

    if (blockIdx.x >= 28) {
        // ---- extra duty: reduce g_pab4 -> g_ab4, and (block 0) compute asq
        int eid = (blockIdx.x - 28) + 2 * blockIdx.y;   // 0..31
        const float4* src = (const float4*)g_pab4;
        for (int idx = eid * 224 + tid; idx < RED4_N; idx += 32 * 224) {
            float4 s = make_float4(0.f, 0.f, 0.f, 0.f);
            #pragma unroll 8
            for (int ck = 0; ck < NCH4; ck++) {
                float4 v = src[(size_t)ck * RED4_N + idx];
                s.x += v.x; s.y += v.y; s.z += v.z; s.w += v.w;
            }
            ((float4*)g_ab4)[idx] = s;
        }
        if (eid == 0) {
            #pragma unroll
            for (int l = 0; l < LL; l++) {
                float s = 0.f;
                for (int c = tid; c < CTOT; c += 224) s += conv_w[l * CTOT + c];
                s_buf[l * 224 + tid] = s;
            }
            __syncthreads();
            for (int off = 112; off >= 7; off >>= 1) {
                if (tid < off)
                    #pragma unroll
                    for (int l = 0; l < LL; l++)
                        s_buf[l * 224 + tid] += s_buf[l * 224 + tid + off];
                __syncthreads();
            }
            if (tid == 0) {
                #pragma unroll
                for (int l = 0; l < LL; l++) {
                    float tot = 0.f;
                    for (int j = 0; j < 7; j++) tot += s_buf[l * 224 + j];
                    g_asq[l] = tot;
                }
            }
        }
        return;
    }

    int ck = blockIdx.y;
    for (int i = tid; i < LL * 64; i += 224)
        s_buf[i] = conv_w[(i / 64) * CTOT + C4 + ck * 64 + (i & 63)];
    __syncthreads();

    int g = blockIdx.x * 224 + tid;   // 0..6271
    int b = g / 196;
    int p = (g % 196) * 4;

    const float* src = l3 + ((size_t)b * C3 + (size_t)ck * 64) * HW + p;

    float4 acc[LL];
    #pragma unroll
    for (int l = 0; l < LL; l++) acc[l] = make_float4(0.f, 0.f, 0.f, 0.f);

    #pragma unroll 2
    for (int ci = 0; ci < 64; ci += 4) {
        float4 x0 = *(const float4*)(src + (size_t)(ci + 0) * HW);
        float4 x1 = *(const float4*)(src + (size_t)(ci + 1) * HW);
        float4 x2 = *(const float4*)(src + (size_t)(ci + 2) * HW);
        float4 x3 = *(const float4*)(src + (size_t)(ci + 3) * HW);
        #pragma unroll
        for (int l = 0; l < LL; l++) {
            float4 w = *(const float4*)&s_buf[l * 64 + ci];
            acc[l].x = fmaf(w.x, x0.x, acc[l].x);
            acc[l].y = fmaf(w.x, x0.y, acc[l].y);
            acc[l].z = fmaf(w.x, x0.z, acc[l].z);
            acc[l].w = fmaf(w.x, x0.w, acc[l].w);
            acc[l].x = fmaf(w.y, x1.x, acc[l].x);
            acc[l].y = fmaf(w.y, x1.y, acc[l].y);
            acc[l].z = fmaf(w.y, x1.z, acc[l].z);
            acc[l].w = fmaf(w.y, x1.w, acc[l].w);
            acc[l].x = fmaf(w.z, x2.x, acc[l].x);
            acc[l].y = fmaf(w.z, x2.y, acc[l].y);
            acc[l].z = fmaf(w.z, x2.z, acc[l].z);
            acc[l].w = fmaf(w.z, x2.w, acc[l].w);
            acc[l].x = fmaf(w.w, x3.x, acc[l].x);
            acc[l].y = fmaf(w.w, x3.y, acc[l].y);
            acc[l].z = fmaf(w.w, x3.z, acc[l].z);
            acc[l].w = fmaf(w.w, x3.w, acc[l].w);
        }
    }
    #pragma unroll
    for (int l = 0; l < LL; l++)
        *(float4*)&g_pab3[((size_t)(ck * BB + b) * LL + l) * HW + p] = acc[l];
}

// ---------------------------------------------------------------------------
// Per-pixel: gather l3 partials, bilinear-upsample reduced l4 ab, softmax.
__global__ void k_softmax(float* __restrict__ maps_out) {
    int t = blockIdx.x * 256 + threadIdx.x;
    int b = t / HW, p = t % HW;
    int y = p / HH, x = p % HH;

    float fy = y * 0.5f - 0.25f;
    int iy = (int)floorf(fy);
    float wy1 = fy - (float)iy;
    float wy0 = 1.f - wy1;
    int y0 = max(iy, 0), y1 = min(iy + 1, H4 - 1);

    float fx = x * 0.5f - 0.25f;
    int ix = (int)floorf(fx);
    float wx1 = fx - (float)ix;
    float wx0 = 1.f - wx1;
    int x0 = max(ix, 0), x1 = min(ix + 1, H4 - 1);

    float logit[LL];
    float mx = -1e30f;
    #pragma unroll
    for (int l = 0; l < LL; l++) {
        const float* a4 = g_ab4 + (size_t)(b * LL + l) * HW4;
        float v = wy0 * (wx0 * a4[y0 * H4 + x0] + wx1 * a4[y0 * H4 + x1])
                + wy1 * (wx0 * a4[y1 * H4 + x0] + wx1 * a4[y1 * H4 + x1]);
        float s3 = 0.f;
        #pragma unroll
        for (int ck = 0; ck < NCH3; ck++)
            s3 += g_pab3[((size_t)(ck * BB + b) * LL + l) * HW + p];
        float lg = 2.f * (v + s3) - g_asq[l];
        logit[l] = lg;
        mx = fmaxf(mx, lg);
    }
    float e[LL], den = 0.f;
    #pragma unroll
    for (int l = 0; l < LL; l++) { e[l] = __expf(logit[l] - mx); den += e[l]; }
    float inv = 1.f / den;
    #pragma unroll
    for (int l = 0; l < LL; l++)
        maps_out[(size_t)(b * LL + l) * HW + p] = e[l] * inv;
}

// ---------------------------------------------------------------------------
// Adjoint bilinear weight: contribution of output index y to input index r.
__device__ __forceinline__ float tapw(int y, int r) {
    float f = y * 0.5f - 0.25f;
    int i0 = (int)floorf(f);
    float w1 = f - (float)i0;
    int c0 = max(i0, 0), c1 = min(i0 + 1, H4 - 1);
    float w = 0.f;
    if (c0 == r) w += 1.f - w1;
    if (c1 == r) w += w1;
    return w;
}

// maps_down[b][l][q] = sum_p coef(p,q) * maps[b][l][p]
__global__ void k_mdown(const float* __restrict__ maps_out) {
    int t = blockIdx.x * 256 + threadIdx.x;
    if (t >= BB * LL * HW4) return;
    int q = t % HW4;
    int l = (t / HW4) % LL;
    int b = t / (HW4 * LL);
    int r = q / H4, c = q % H4;
    const float* mp = maps_out + (size_t)(b * LL + l) * HW;

    int ylo = max(0, 2 * r - 1), yhi = min(HH - 1, 2 * r + 2);
    int xlo = max(0, 2 * c - 1), xhi = min(HH - 1, 2 * c + 2);
    float s = 0.f;
    for (int y = ylo; y <= yhi; y++) {
        float wy = tapw(y, r);
        for (int x = xlo; x <= xhi; x++)
            s += wy * tapw(x, c) * mp[y * HH + x];
    }
    g_mdown[t] = s;
}

// ---------------------------------------------------------------------------
// all_features for l3 channels (c >= 2048): 4-channel x float2-pixel warps.
// block 256 (8 warps) covers 32 channels; grid (32, 32).
__global__ void __launch_bounds__(256)
k_feat3(const float* __restrict__ l3, const float* __restrict__ maps_out,
        const float* __restrict__ modulation, float* __restrict__ af_out) {
    __shared__ __align__(16) float mp_s[LL * HW];   // 28224 B
    int b = blockIdx.y;
    {
        const float4* s4 = (const float4*)(maps_out + (size_t)b * LL * HW);
        float4* d4 = (float4*)mp_s;
        for (int i = threadIdx.x; i < LL * HW / 4; i += 256) d4[i] = s4[i];
    }
    __syncthreads();

    int warp = threadIdx.x >> 5, lane = threadIdx.x & 31;
    int cl = blockIdx.x * 32 + warp * 4;          // local channel base (0..1020)
    const float* base = l3 + ((size_t)b * C3 + cl) * HW;

    float2 acc[4][LL];
    #pragma unroll
    for (int cc = 0; cc < 4; cc++)
        #pragma unroll
        for (int l = 0; l < LL; l++) acc[cc][l] = make_float2(0.f, 0.f);

    // 12 full iterations (768 pixels), 64 px per iter
    #pragma unroll 2
    for (int p0 = 0; p0 < 768; p0 += 64) {
        int p = p0 + 2 * lane;
        float2 m[LL];
        #pragma unroll
        for (int l = 0; l < LL; l++) m[l] = *(const float2*)&mp_s[l * HW + p];
        #pragma unroll
        for (int cc = 0; cc < 4; cc++) {
            float2 xv = *(const float2*)(base + (size_t)cc * HW + p);
            #pragma unroll
            for (int l = 0; l < LL; l++) {
                acc[cc][l].x = fmaf(m[l].x, xv.x, acc[cc][l].x);
                acc[cc][l].y = fmaf(m[l].y, xv.y, acc[cc][l].y);
            }
        }
    }
    // tail: 16 px (lanes 0..7)
    if (lane < 8) {
        int p = 768 + 2 * lane;
        float2 m[LL];
        #pragma unroll
        for (int l = 0; l < LL; l++) m[l] = *(const float2*)&mp_s[l * HW + p];
        #pragma unroll
        for (int cc = 0; cc < 4; cc++) {
            float2 xv = *(const float2*)(base + (size_t)cc * HW + p);
            #pragma unroll
            for (int l = 0; l < LL; l++) {
                acc[cc][l].x = fmaf(m[l].x, xv.x, acc[cc][l].x);
                acc[cc][l].y = fmaf(m[l].y, xv.y, acc[cc][l].y);
            }
        }
    }

    // collapse float2 then butterfly across lanes
    float s[4][LL];
    #pragma unroll
    for (int cc = 0; cc < 4; cc++)
        #pragma unroll
        for (int l = 0; l < LL; l++) s[cc][l] = acc[cc][l].x + acc[cc][l].y;
    #pragma unroll
    for (int off = 16; off; off >>= 1)
        #pragma unroll
        for (int cc = 0; cc < 4; cc++)
            #pragma unroll
            for (int l = 0; l < LL; l++)
                s[cc][l] += __shfl_xor_sync(0xffffffffu, s[cc][l], off);

    if (lane < 4) {
        int cc = lane;
        int c = C4 + cl + cc;
        float mf = 0.f;
        #pragma unroll
        for (int l = 0; l < LL; l++) {
            float v = s[cc][l] * (1.f / (float)HW);
            af_out[((size_t)b * CTOT + c) * LL + l] = v;
            if (l < LL - 1) mf = fmaf(v, modulation[c * LL + l], mf);
        }
        g_meanf[(size_t)b * CTOT + c] = mf * (1.f / 8.f);
    }
}

// all_features for l4 channels (c < 2048) via adjoint maps on 14x14.
// 4-channel x float2-pixel warps. grid (64, 32), block 256.
__global__ void __launch_bounds__(256)
k_feat4(const float* __restrict__ l4, const float* __restrict__ modulation,
        float* __restrict__ af_out) {
    __shared__ __align__(16) float md_s[LL * HW4];
    int b = blockIdx.y;
    {
        const float4* s4 = (const float4*)(g_mdown + (size_t)b * LL * HW4);
        float4* d4 = (float4*)md_s;
        for (int i = threadIdx.x; i < LL * HW4 / 4; i += 256) d4[i] = s4[i];
    }
    __syncthreads();

    int warp = threadIdx.x >> 5, lane = threadIdx.x & 31;
    int c0 = blockIdx.x * 32 + warp * 4;          // 0..2044
    const float* base = l4 + ((size_t)b * C4 + c0) * HW4;

    float2 acc[4][LL];
    #pragma unroll
    for (int cc = 0; cc < 4; cc++)
        #pragma unroll
        for (int l = 0; l < LL; l++) acc[cc][l] = make_float2(0.f, 0.f);

    // 3 full iterations (192 px)
    #pragma unroll
    for (int p0 = 0; p0 < 192; p0 += 64) {
        int p = p0 + 2 * lane;
        float2 m[LL];
        #pragma unroll
        for (int l = 0; l < LL; l++) m[l] = *(const float2*)&md_s[l * HW4 + p];
        #pragma unroll
        for (int cc = 0; cc < 4; cc++) {
            float2 xv = *(const float2*)(base + (size_t)cc * HW4 + p);
            #pragma unroll
            for (int l = 0; l < LL; l++) {
                acc[cc][l].x = fmaf(m[l].x, xv.x, acc[cc][l].x);
                acc[cc][l].y = fmaf(m[l].y, xv.y, acc[cc][l].y);
            }
        }
    }
    // tail: 4 px (lanes 0..1)
    if (lane < 2) {
        int p = 192 + 2 * lane;
        float2 m[LL];
        #pragma unroll
        for (int l = 0; l < LL; l++) m[l] = *(const float2*)&md_s[l * HW4 + p];
        #pragma unroll
        for (int cc = 0; cc < 4; cc++) {
            float2 xv = *(const float2*)(base + (size_t)cc * HW4 + p);
            #pragma unroll
            for (int l = 0; l < LL; l++) {
                acc[cc][l].x = fmaf(m[l].x, xv.x, acc[cc][l].x);
                acc[cc][l].y = fmaf(m[l].y, xv.y, acc[cc][l].y);
            }
        }
    }

    float s[4][LL];
    #pragma unroll
    for (int cc = 0; cc < 4; cc++)
        #pragma unroll
        for (int l = 0; l < LL; l++) s[cc][l] = acc[cc][l].x + acc[cc][l].y;
    #pragma unroll
    for (int off = 16; off; off >>= 1)
        #pragma unroll
        for (int cc = 0; cc < 4; cc++)
            #pragma unroll
            for (int l = 0; l < LL; l++)
                s[cc][l] += __shfl_xor_sync(0xffffffffu, s[cc][l], off);

    if (lane < 4) {
        int cc = lane;
        int c = c0 + cc;
        float mf = 0.f;
        #pragma unroll
        for (int l = 0; l < LL; l++) {
            float v = s[cc][l] * (1.f / (float)HW);
            af_out[((size_t)b * CTOT + c) * LL + l] = v;
            if (l < LL - 1) mf = fmaf(v, modulation[c * LL + l], mf);
        }
        g_meanf[(size_t)b * CTOT + c] = mf * (1.f / 8.f);
    }
}

// ---------------------------------------------------------------------------
// attr_scores = mean_features @ attr_w^T + attr_b.
__global__ void k_attr(const float* __restrict__ attr_w, const float* __restrict__ attr_b,
                       float* __restrict__ attr_out) {
    int a = blockIdx.x;
    int warp = threadIdx.x >> 5, lane = threadIdx.x & 31;
    const float* wrow = attr_w + (size_t)a * CTOT;
    float acc[8];
    #pragma unroll
    for (int j = 0; j < 8; j++) acc[j] = 0.f;
    for (int k = lane; k < CTOT; k += 32) {
        float wv = wrow[k];
        #pragma unroll
        for (int j = 0; j < 8; j++)
            acc[j] = fmaf(wv, g_meanf[(size_t)(warp * 8 + j) * CTOT + k], acc[j]);
    }
    #pragma unroll
    for (int j = 0; j < 8; j++)
        #pragma unroll
        for (int off = 16; off; off >>= 1)
            acc[j] += __shfl_down_sync(0xffffffffu, acc[j], off);
    if (lane == 0) {
        float bias = attr_b[a];
        #pragma unroll
        for (int j = 0; j < 8; j++)
            attr_out[(size_t)(warp * 8 + j) * NA + a] = acc[j] + bias;
    }
}

// class_scores = attr_scores @ class_w^T
__global__ void k_class(const float* __restrict__ attr_out, const float* __restrict__ class_w,
                        float* __restrict__ class_out) {
    int t = blockIdx.x * 256 + threadIdx.x;
    if (t >= BB * NC) return;
    int b = t / NC, nc = t % NC;
    const float* ar = attr_out + (size_t)b * NA;
    const float* wr = class_w + (size_t)nc * NA;
    float s = 0.f;
    #pragma unroll 4
    for (int k = 0; k < NA; k++) s = fmaf(ar[k], wr[k], s);
    class_out[t] = s;
}

// ---------------------------------------------------------------------------
extern "C" void kernel_launch(void* const* d_in, const int* in_sizes, int n_in,
                              void* d_out, int out_size) {
    const float* l3     = (const float*)d_in[0];
    const float* l4     = (const float*)d_in[1];
    const float* conv_w = (const float*)d_in[2];
    const float* modu   = (const float*)d_in[3];
    const float* attr_w = (const float*)d_in[4];
    const float* attr_b = (const float*)d_in[5];
    const float* class_w= (const float*)d_in[6];

    float* out = (float*)d_out;
    float* attr_out  = out + OFF_ATTR;
    float* class_out = out + OFF_CLASS;
    float* maps_out  = out + OFF_MAPS;
    float* af_out    = out + OFF_AF;

    // 8 launches; k_feat3 is 4th (ncu capture slot).
    k_ab4<<<dim3(14, NCH4), 224>>>(l4, conv_w);
    k_ab3<<<dim3(30, NCH3), 224>>>(l3, conv_w);     // + red4 + asq in extra blocks
    k_softmax<<<98, 256>>>(maps_out);
    k_feat3<<<dim3(32, BB), 256>>>(l3, maps_out, modu, af_out);
    k_mdown<<<(BB * LL * HW4 + 255) / 256, 256>>>(maps_out);
    k_feat4<<<dim3(64, BB), 256>>>(l4, modu, af_out);
    k_attr<<<NA, 128>>>(attr_w, attr_b, attr_out);
    k_class<<<(BB * NC + 255) / 256, 256>>>(attr_out, class_w, class_out);
}